// round 3
// baseline (speedup 1.0000x reference)
#include <cuda_runtime.h>
#include <cuda_bf16.h>
#include <math.h>

#define B_  64
#define S_  512
#define D_  768
#define H_  12
#define DH_ 64
#define NF_ 32
#define NL_ 12
#define OUT_ 512

static const int BS_  = B_ * S_;        // 32768
static const int BSD_ = B_ * S_ * D_;   // 25165824

// ---------------- scratch (allowed: __device__ globals) ----------------
__device__ float g_h [B_*S_*D_];
__device__ float g_q [B_*S_*D_];
__device__ float g_k [B_*S_*D_];
__device__ float g_v [B_*S_*D_];
__device__ float g_t1[B_*S_*D_];
__device__ float g_ff[B_*S_*D_];
__device__ float g_pq[B_*S_*H_*NF_];
__device__ float g_pk[B_*S_*H_*NF_];
__device__ float g_kv[B_*H_*NF_*DH_];
__device__ float g_ps[B_*H_*NF_];
__device__ float g_pool[B_*D_];

// ---------------- embedding ----------------
__global__ void embed_kernel(const int* __restrict__ x, const float* __restrict__ emb,
                             float* __restrict__ h)
{
    long i = (long)blockIdx.x * blockDim.x + threadIdx.x;
    if (i < (long)BSD_) {
        int bs = (int)(i / D_);
        int d  = (int)(i % D_);
        h[i] = emb[(long)x[bs] * D_ + d];
    }
}

// ---------------- SGEMM: C = A[MxK] @ B[KxN] + bias, opt. exact GELU ----------------
// M%128==0, N%128==0, K%8==0 assumed (32768 x 768 x 768 here).
template<int ACT>
__global__ void __launch_bounds__(256, 2)
sgemm_kernel(const float* __restrict__ A, const float* __restrict__ Bm,
             const float* __restrict__ bias, float* __restrict__ C,
             int M, int N, int K)
{
    __shared__ float As[2][8][128];
    __shared__ float Bs[2][8][128];

    const int tid = threadIdx.x;
    const int bx = blockIdx.x, by = blockIdx.y;
    const int tx = tid & 15, ty = tid >> 4;

    const int arow = tid >> 1;           // 0..127
    const int acol = (tid & 1) << 2;     // 0 or 4
    const int brow = tid >> 5;           // 0..7
    const int bcol = (tid & 31) << 2;    // 0..124

    const float* Aptr = A  + (size_t)(by * 128 + arow) * K + acol;
    const float* Bptr = Bm + (size_t)brow * N + bx * 128 + bcol;

    float acc[8][8];
    #pragma unroll
    for (int i = 0; i < 8; i++)
        #pragma unroll
        for (int j = 0; j < 8; j++) acc[i][j] = 0.f;

    // preload tile 0
    {
        float4 a4 = *(const float4*)(Aptr);
        float4 b4 = *(const float4*)(Bptr);
        As[0][acol + 0][arow] = a4.x;
        As[0][acol + 1][arow] = a4.y;
        As[0][acol + 2][arow] = a4.z;
        As[0][acol + 3][arow] = a4.w;
        *(float4*)&Bs[0][brow][bcol] = b4;
    }
    __syncthreads();

    const int nIter = K >> 3;
    int buf = 0;
    for (int t = 0; t < nIter; ++t) {
        float4 na, nb;
        bool more = (t + 1 < nIter);
        if (more) {
            na = *(const float4*)(Aptr + (size_t)(t + 1) * 8);
            nb = *(const float4*)(Bptr + (size_t)(t + 1) * 8 * N);
        }
        #pragma unroll
        for (int kk = 0; kk < 8; ++kk) {
            float a[8], b[8];
            *(float4*)&a[0] = *(const float4*)&As[buf][kk][ty * 8];
            *(float4*)&a[4] = *(const float4*)&As[buf][kk][ty * 8 + 4];
            *(float4*)&b[0] = *(const float4*)&Bs[buf][kk][tx * 8];
            *(float4*)&b[4] = *(const float4*)&Bs[buf][kk][tx * 8 + 4];
            #pragma unroll
            for (int i = 0; i < 8; i++)
                #pragma unroll
                for (int j = 0; j < 8; j++)
                    acc[i][j] = fmaf(a[i], b[j], acc[i][j]);
        }
        if (more) {
            int nbuf = buf ^ 1;
            As[nbuf][acol + 0][arow] = na.x;
            As[nbuf][acol + 1][arow] = na.y;
            As[nbuf][acol + 2][arow] = na.z;
            As[nbuf][acol + 3][arow] = na.w;
            *(float4*)&Bs[nbuf][brow][bcol] = nb;
        }
        __syncthreads();
        buf ^= 1;
    }

    const int crow0 = by * 128 + ty * 8;
    const int ccol0 = bx * 128 + tx * 8;
    #pragma unroll
    for (int i = 0; i < 8; i++) {
        #pragma unroll
        for (int j0 = 0; j0 < 8; j0 += 4) {
            float o[4];
            #pragma unroll
            for (int j = 0; j < 4; j++) {
                float v = acc[i][j0 + j] + bias[ccol0 + j0 + j];
                if (ACT == 1) v = 0.5f * v * (1.0f + erff(v * 0.70710678118654752f));
                o[j] = v;
            }
            *(float4*)(C + (size_t)(crow0 + i) * N + ccol0 + j0) = *(float4*)o;
        }
    }
}

// ---------------- rotary (in smem) + feature maps: pq=relu(q@om), pk=relu(k@om)*mask ----------------
__global__ void feat_kernel(const float* __restrict__ q, const float* __restrict__ k,
                            const float* __restrict__ om, const float* __restrict__ mask,
                            float* __restrict__ pq, float* __restrict__ pk)
{
    const int bs  = blockIdx.x;        // 0..BS-1
    const int t   = bs % S_;           // position
    const int tid = threadIdx.x;       // 384 threads

    __shared__ float sq[D_];
    __shared__ float sk[D_];
    __shared__ float som[DH_ * NF_];

    for (int i = tid; i < D_; i += 384) {
        sq[i] = q[(size_t)bs * D_ + i];
        sk[i] = k[(size_t)bs * D_ + i];
    }
    for (int i = tid; i < DH_ * NF_; i += 384) som[i] = om[i];
    __syncthreads();

    // rotary: each thread owns exactly one (head, j) pair -> no cross-thread hazard
    {
        const int hh = tid >> 5, j = tid & 31;
        const int base = hh * DH_ + j;
        float invf = expf(-(float)j * 0.28782313662425572f); // ln(1e4)/32
        float ang = (float)t * invf;
        float c = cosf(ang), s = sinf(ang);
        float qa = sq[base], qb = sq[base + 32];
        float ka = sk[base], kb = sk[base + 32];
        sq[base]      = qa * c - qb * s;
        sq[base + 32] = qb * c + qa * s;
        sk[base]      = ka * c - kb * s;
        sk[base + 32] = kb * c + ka * s;
    }
    __syncthreads();

    const int hh = tid >> 5, f = tid & 31;
    float aq = 0.f, ak = 0.f;
    #pragma unroll 16
    for (int d = 0; d < DH_; ++d) {
        float w = som[d * NF_ + f];
        aq = fmaf(sq[hh * DH_ + d], w, aq);
        ak = fmaf(sk[hh * DH_ + d], w, ak);
    }
    float m = mask[bs];
    pq[((size_t)bs * H_ + hh) * NF_ + f] = fmaxf(aq, 0.f);
    pk[((size_t)bs * H_ + hh) * NF_ + f] = fmaxf(ak, 0.f) * m;
}

// ---------------- kv[b,h,f,d] = sum_s pk*v ; ps[b,h,f] = sum_s pk ----------------
__global__ void kv_kernel(const float* __restrict__ pk, const float* __restrict__ v,
                          float* __restrict__ kv, float* __restrict__ ps)
{
    const int b = blockIdx.x / H_;
    const int h = blockIdx.x % H_;
    const int tid = threadIdx.x;      // 256

    __shared__ float spk[32][NF_];
    __shared__ float sv [32][DH_];

    const int f  = tid >> 3;          // 0..31
    const int d0 = (tid & 7) * 8;     // 0..56

    float acc[8];
    #pragma unroll
    for (int i = 0; i < 8; i++) acc[i] = 0.f;
    float psum = 0.f;

    for (int s0 = 0; s0 < S_; s0 += 32) {
        for (int i = tid; i < 32 * NF_; i += 256) {
            int sl = i >> 5, ff = i & 31;
            spk[sl][ff] = pk[(((size_t)(b * S_ + s0 + sl)) * H_ + h) * NF_ + ff];
        }
        for (int i = tid; i < 32 * DH_; i += 256) {
            int sl = i >> 6, dd = i & 63;
            sv[sl][dd] = v[((size_t)(b * S_ + s0 + sl)) * D_ + h * DH_ + dd];
        }
        __syncthreads();
        #pragma unroll 8
        for (int sl = 0; sl < 32; ++sl) {
            float pv = spk[sl][f];
            psum += pv;
            #pragma unroll
            for (int i = 0; i < 8; i++)
                acc[i] = fmaf(pv, sv[sl][d0 + i], acc[i]);
        }
        __syncthreads();
    }
    #pragma unroll
    for (int i = 0; i < 8; i++)
        kv[(((size_t)(b * H_ + h)) * NF_ + f) * DH_ + d0 + i] = acc[i];
    if ((tid & 7) == 0) ps[((size_t)(b * H_ + h)) * NF_ + f] = psum;
}

// ---------------- att[b,s,h*64+d] = (1/(pq.ps + eps)) * sum_f pq*kv ----------------
__global__ void att_kernel(const float* __restrict__ pq, const float* __restrict__ kv,
                           const float* __restrict__ ps, float* __restrict__ att)
{
    const int b = blockIdx.x / H_;
    const int h = blockIdx.x % H_;
    const int tid = threadIdx.x;   // 256

    __shared__ float skv[NF_ * DH_];
    __shared__ float sps[NF_];
    __shared__ float spq[4][NF_];

    for (int i = tid; i < NF_ * DH_; i += 256)
        skv[i] = kv[((size_t)(b * H_ + h)) * NF_ * DH_ + i];
    if (tid < NF_) sps[tid] = ps[((size_t)(b * H_ + h)) * NF_ + tid];
    __syncthreads();

    const int sl = tid >> 6;   // 0..3
    const int d  = tid & 63;

    for (int s0 = 0; s0 < S_; s0 += 4) {
        if (tid < 128) {
            int l = tid >> 5, ff = tid & 31;
            spq[l][ff] = pq[(((size_t)(b * S_ + s0 + l)) * H_ + h) * NF_ + ff];
        }
        __syncthreads();
        float za = 0.f, aa = 0.f;
        #pragma unroll 8
        for (int ff = 0; ff < NF_; ++ff) {
            float pv = spq[sl][ff];
            za = fmaf(pv, sps[ff], za);
            aa = fmaf(pv, skv[ff * DH_ + d], aa);
        }
        float z = 1.0f / (za + 1e-6f);
        att[((size_t)(b * S_ + s0 + sl)) * D_ + h * DH_ + d] = aa * z;
        __syncthreads();
    }
}

// ---------------- h = LN(h + r) * gamma + beta  (in place on h) ----------------
__global__ void addln_kernel(float* __restrict__ h, const float* __restrict__ r,
                             const float* __restrict__ gam, const float* __restrict__ bet)
{
    const int row = blockIdx.x;
    const int tid = threadIdx.x;   // 256
    const size_t base = (size_t)row * D_;

    float x0 = h[base + tid]       + r[base + tid];
    float x1 = h[base + tid + 256] + r[base + tid + 256];
    float x2 = h[base + tid + 512] + r[base + tid + 512];

    __shared__ float red[8];
    float s = x0 + x1 + x2;
    #pragma unroll
    for (int o = 16; o; o >>= 1) s += __shfl_xor_sync(0xffffffffu, s, o);
    if ((tid & 31) == 0) red[tid >> 5] = s;
    __syncthreads();
    float tot = red[0] + red[1] + red[2] + red[3] + red[4] + red[5] + red[6] + red[7];
    float mean = tot * (1.0f / 768.0f);

    float d0 = x0 - mean, d1 = x1 - mean, d2 = x2 - mean;
    float s2 = d0 * d0 + d1 * d1 + d2 * d2;
    #pragma unroll
    for (int o = 16; o; o >>= 1) s2 += __shfl_xor_sync(0xffffffffu, s2, o);
    __syncthreads();   // all reads of red[] done before overwrite
    if ((tid & 31) == 0) red[tid >> 5] = s2;
    __syncthreads();
    float var = (red[0] + red[1] + red[2] + red[3] + red[4] + red[5] + red[6] + red[7]) * (1.0f / 768.0f);
    float inv = rsqrtf(var + 1e-5f);

    h[base + tid]       = d0 * inv * gam[tid]       + bet[tid];
    h[base + tid + 256] = d1 * inv * gam[tid + 256] + bet[tid + 256];
    h[base + tid + 512] = d2 * inv * gam[tid + 512] + bet[tid + 512];
}

// ---------------- masked mean pool ----------------
__global__ void pool_kernel(const float* __restrict__ h, const float* __restrict__ mask,
                            float* __restrict__ pool)
{
    const int b = blockIdx.x;
    const int tid = threadIdx.x;   // 256
    float acc0 = 0.f, acc1 = 0.f, acc2 = 0.f, dn = 0.f;
    for (int s = 0; s < S_; ++s) {
        float m = mask[b * S_ + s];
        dn += m;
        const float* hp = h + ((size_t)(b * S_ + s)) * D_;
        acc0 += hp[tid]       * m;
        acc1 += hp[tid + 256] * m;
        acc2 += hp[tid + 512] * m;
    }
    dn = fmaxf(dn, 1e-9f);
    float idn = 1.0f / dn;
    pool[(size_t)b * D_ + tid]       = acc0 * idn;
    pool[(size_t)b * D_ + tid + 256] = acc1 * idn;
    pool[(size_t)b * D_ + tid + 512] = acc2 * idn;
}

// ---------------- final: out = relu(pool @ Wl + bl) ----------------
__global__ void final_kernel(const float* __restrict__ pool, const float* __restrict__ Wl,
                             const float* __restrict__ bl, float* __restrict__ out)
{
    const int b = blockIdx.x;
    const int o = threadIdx.x;   // 512
    __shared__ float sp[D_];
    for (int i = o; i < D_; i += 512) sp[i] = pool[(size_t)b * D_ + i];
    __syncthreads();
    float acc = bl[o];
    #pragma unroll 8
    for (int k = 0; k < D_; ++k)
        acc = fmaf(sp[k], Wl[(size_t)k * OUT_ + o], acc);
    out[(size_t)b * OUT_ + o] = fmaxf(acc, 0.f);
}

// ---------------- host ----------------
extern "C" void kernel_launch(void* const* d_in, const int* in_sizes, int n_in,
                              void* d_out, int out_size)
{
    const int*   x     = (const int*)  d_in[0];
    const float* mask  = (const float*)d_in[1];
    const float* tok   = (const float*)d_in[2];
    const float* Wq    = (const float*)d_in[3];
    const float* bq    = (const float*)d_in[4];
    const float* Wk    = (const float*)d_in[5];
    const float* bk    = (const float*)d_in[6];
    const float* Wv    = (const float*)d_in[7];
    const float* bv    = (const float*)d_in[8];
    const float* Wo    = (const float*)d_in[9];
    const float* bo    = (const float*)d_in[10];
    const float* omega = (const float*)d_in[11];
    const float* ln1s  = (const float*)d_in[12];
    const float* ln1b  = (const float*)d_in[13];
    const float* W1    = (const float*)d_in[14];
    const float* b1    = (const float*)d_in[15];
    const float* W2    = (const float*)d_in[16];
    const float* b2    = (const float*)d_in[17];
    const float* ln2s  = (const float*)d_in[18];
    const float* ln2b  = (const float*)d_in[19];
    const float* Wl    = (const float*)d_in[20];
    const float* bl    = (const float*)d_in[21];

    float *h, *q, *k, *v, *t1, *ff, *pq, *pk, *kv, *ps, *pool;
    cudaGetSymbolAddress((void**)&h,  g_h);
    cudaGetSymbolAddress((void**)&q,  g_q);
    cudaGetSymbolAddress((void**)&k,  g_k);
    cudaGetSymbolAddress((void**)&v,  g_v);
    cudaGetSymbolAddress((void**)&t1, g_t1);
    cudaGetSymbolAddress((void**)&ff, g_ff);
    cudaGetSymbolAddress((void**)&pq, g_pq);
    cudaGetSymbolAddress((void**)&pk, g_pk);
    cudaGetSymbolAddress((void**)&kv, g_kv);
    cudaGetSymbolAddress((void**)&ps, g_ps);
    cudaGetSymbolAddress((void**)&pool, g_pool);

    const int M = BS_, N = D_, K = D_;
    dim3 gGemm(N / 128, M / 128);   // (6, 256)

    embed_kernel<<<(BSD_ + 255) / 256, 256>>>(x, tok, h);

    for (int l = 0; l < NL_; ++l) {
        const float* lWq = Wq + (size_t)l * D_ * D_;
        const float* lWk = Wk + (size_t)l * D_ * D_;
        const float* lWv = Wv + (size_t)l * D_ * D_;
        const float* lWo = Wo + (size_t)l * D_ * D_;
        const float* lW1 = W1 + (size_t)l * D_ * D_;
        const float* lW2 = W2 + (size_t)l * D_ * D_;
        const float* lbq = bq + (size_t)l * D_;
        const float* lbk = bk + (size_t)l * D_;
        const float* lbv = bv + (size_t)l * D_;
        const float* lbo = bo + (size_t)l * D_;
        const float* lb1 = b1 + (size_t)l * D_;
        const float* lb2 = b2 + (size_t)l * D_;
        const float* lom = omega + (size_t)l * DH_ * NF_;
        const float* l1s = ln1s + (size_t)l * D_;
        const float* l1b = ln1b + (size_t)l * D_;
        const float* l2s = ln2s + (size_t)l * D_;
        const float* l2b = ln2b + (size_t)l * D_;

        sgemm_kernel<0><<<gGemm, 256>>>(h, lWq, lbq, q, M, N, K);
        sgemm_kernel<0><<<gGemm, 256>>>(h, lWk, lbk, k, M, N, K);
        sgemm_kernel<0><<<gGemm, 256>>>(h, lWv, lbv, v, M, N, K);

        feat_kernel<<<BS_, 384>>>(q, k, lom, mask, pq, pk);
        kv_kernel<<<B_ * H_, 256>>>(pk, v, kv, ps);
        att_kernel<<<B_ * H_, 256>>>(pq, kv, ps, t1);

        sgemm_kernel<0><<<gGemm, 256>>>(t1, lWo, lbo, q, M, N, K);  // reuse q as proj out
        addln_kernel<<<BS_, 256>>>(h, q, l1s, l1b);

        sgemm_kernel<1><<<gGemm, 256>>>(h, lW1, lb1, ff, M, N, K);  // GELU epilogue
        sgemm_kernel<0><<<gGemm, 256>>>(ff, lW2, lb2, t1, M, N, K);
        addln_kernel<<<BS_, 256>>>(h, t1, l2s, l2b);
    }

    pool_kernel<<<B_, 256>>>(h, mask, pool);
    final_kernel<<<B_, 512>>>(pool, Wl, bl, (float*)d_out);
}